// round 14
// baseline (speedup 1.0000x reference)
#include <cuda_runtime.h>
#include <cuda_bf16.h>
#include <cstdint>

#define N_NODES 100000
#define HID     128
#define N_EDGES 1600000
#define NE4 (N_EDGES / 4) // 400000 int4 elements
#define TILES   782       // ceil(100000/128)
#define NJOBS   (2 * TILES)
#define GEMM_GRID 148
#define XPAD 132          // conflict-free tf32 fragment LDS
#define SLOT 64           // fixed bucket capacity per row (P(overflow)~1e-13)

// Scratch (__device__ globals; zero-initialized at module load; no allocs)
__device__ float          g_SI[2u * N_NODES * HID];     // [0]=S, [1]=I (fp32)
__device__ __nv_bfloat16  g_Ibf[(size_t)N_NODES * HID]; // bf16 mirror of I
__device__ int   g_cnt[N_NODES];                 // per-row edge count/cursor
__device__ int   g_scols[(size_t)N_NODES * SLOT]; // fixed-slot buckets (25.6MB)

__device__ __forceinline__ unsigned smem_u32(const void* p) {
    unsigned a;
    asm("{ .reg .u64 t; cvta.to.shared.u64 t, %1; cvt.u32.u64 %0, t; }"
        : "=r"(a) : "l"(p));
    return a;
}

__device__ __forceinline__ unsigned to_tf32(float f) {
    unsigned r;
    asm("cvt.rna.tf32.f32 %0, %1;" : "=r"(r) : "f"(f));
    return r;
}

__device__ __forceinline__ void mma_tf32(float* d, const unsigned* a,
                                         const unsigned* b) {
    asm volatile(
        "mma.sync.aligned.m16n8k8.row.col.f32.tf32.tf32.f32 "
        "{%0,%1,%2,%3}, {%4,%5,%6,%7}, {%8,%9}, {%0,%1,%2,%3};\n"
        : "+f"(d[0]), "+f"(d[1]), "+f"(d[2]), "+f"(d[3])
        : "r"(a[0]), "r"(a[1]), "r"(a[2]), "r"(a[3]), "r"(b[0]), "r"(b[1]));
}

// ---------------------------------------------------------------------------
// Persistent tf32 tensor-core GEMM: S/I = sigmoid(x[s] @ W^T + b), s in {0,1}
// s=1 additionally mirrors I to bf16 (gather operand).
// ---------------------------------------------------------------------------
__global__ void __launch_bounds__(256, 1)
gemm_tc_kernel(const float* __restrict__ x,
               const float* __restrict__ W,
               const float* __restrict__ b) {
    extern __shared__ float sm[];
    float* Ws  = sm;                          // 128*XPAD (tf32-rounded bits)
    float* Xs0 = sm + 128 * XPAD;
    float* Xs1 = Xs0 + 128 * XPAD;
    float* Bs  = Xs1 + 128 * XPAD;            // 128

    const int tid  = threadIdx.x;
    const int wid  = tid >> 5;
    const int lane = tid & 31;
    const int qrow = lane >> 2;    // 0..7
    const int qcol = lane & 3;     // 0..3
    const int warpM = wid & 1;     // 2 x 64 rows
    const int warpN = wid >> 1;    // 4 x 32 cols

    for (int idx = tid; idx < 128 * 128; idx += 256) {
        int c = idx >> 7, k = idx & 127;
        Ws[c * XPAD + k] = __uint_as_float(to_tf32(W[idx]));
    }
    if (tid < 128) Bs[tid] = b[tid];

    auto issue_tile = [&](int job, float* dst) {
        const int s    = (job >= TILES) ? 1 : 0;
        const int row0 = (job - s * TILES) * 128;
        const char* src = (const char*)(x + ((size_t)s * N_NODES + row0) * HID);
        unsigned d = smem_u32(dst);
#pragma unroll
        for (int i = 0; i < 16; i++) {
            int c   = tid + i * 256;       // 4096 16B chunks
            int row = c >> 5, col16 = c & 31;
            asm volatile("cp.async.cg.shared.global [%0], [%1], 16;"
                         :: "r"(d + (row * XPAD * 4 + col16 * 16)),
                            "l"(src + (size_t)row * 512 + col16 * 16)
                         : "memory");
        }
        asm volatile("cp.async.commit_group;" ::: "memory");
    };

    int job = blockIdx.x;
    if (job < NJOBS) issue_tile(job, Xs0);
    int buf = 0;

    for (; job < NJOBS; job += GEMM_GRID) {
        const int nxt = job + GEMM_GRID;
        float* Xc = buf ? Xs1 : Xs0;
        if (nxt < NJOBS) {
            issue_tile(nxt, buf ? Xs0 : Xs1);
            asm volatile("cp.async.wait_group 1;" ::: "memory");
        } else {
            asm volatile("cp.async.wait_group 0;" ::: "memory");
        }
        __syncthreads();

        float acc[4][4][4];
#pragma unroll
        for (int i = 0; i < 4; i++)
#pragma unroll
            for (int j = 0; j < 4; j++)
#pragma unroll
                for (int q = 0; q < 4; q++) acc[i][j][q] = 0.f;

#pragma unroll 2
        for (int k0 = 0; k0 < 128; k0 += 8) {
            unsigned af[4][4], bf[4][2];
#pragma unroll
            for (int i = 0; i < 4; i++) {
                const float* base = Xc + (warpM * 64 + i * 16 + qrow) * XPAD + k0 + qcol;
                af[i][0] = to_tf32(base[0]);
                af[i][1] = to_tf32(base[8 * XPAD]);
                af[i][2] = to_tf32(base[4]);
                af[i][3] = to_tf32(base[8 * XPAD + 4]);
            }
#pragma unroll
            for (int j = 0; j < 4; j++) {
                const float* base = Ws + (warpN * 32 + j * 8 + qrow) * XPAD + k0 + qcol;
                bf[j][0] = __float_as_uint(base[0]);
                bf[j][1] = __float_as_uint(base[4]);
            }
#pragma unroll
            for (int i = 0; i < 4; i++)
#pragma unroll
                for (int j = 0; j < 4; j++)
                    mma_tf32(acc[i][j], af[i], bf[j]);
        }

        const int s    = (job >= TILES) ? 1 : 0;
        const int row0 = (job - s * TILES) * 128;
        float* outS = g_SI + ((size_t)s * N_NODES + row0) * HID;
        __nv_bfloat16* outB = g_Ibf + (size_t)row0 * HID;
#pragma unroll
        for (int i = 0; i < 4; i++) {
            const int r0 = warpM * 64 + i * 16 + qrow;
#pragma unroll
            for (int j = 0; j < 4; j++) {
                const int c  = warpN * 32 + j * 8 + 2 * qcol;
                const float b0 = Bs[c], b1 = Bs[c + 1];
                if (row0 + r0 < N_NODES) {
                    float2 v = make_float2(
                        1.f / (1.f + __expf(-(acc[i][j][0] + b0))),
                        1.f / (1.f + __expf(-(acc[i][j][1] + b1))));
                    *(float2*)(outS + (size_t)r0 * HID + c) = v;
                    if (s)
                        *(__nv_bfloat162*)(outB + (size_t)r0 * HID + c) =
                            __float22bfloat162_rn(v);
                }
                if (row0 + r0 + 8 < N_NODES) {
                    float2 v = make_float2(
                        1.f / (1.f + __expf(-(acc[i][j][2] + b0))),
                        1.f / (1.f + __expf(-(acc[i][j][3] + b1))));
                    *(float2*)(outS + (size_t)(r0 + 8) * HID + c) = v;
                    if (s)
                        *(__nv_bfloat162*)(outB + (size_t)(r0 + 8) * HID + c) =
                            __float22bfloat162_rn(v);
                }
            }
        }
        __syncthreads();
        buf ^= 1;
    }
}

// ---------------------------------------------------------------------------
// Fused hist+bucket: fixed 64-slot bucket per row, one edge pass, no scan.
// g_cnt arrives zeroed (module zero-init on call 1; gather resets it after).
// ---------------------------------------------------------------------------
__global__ void __launch_bounds__(256)
bucket_kernel(const int* __restrict__ rows, const int* __restrict__ cols) {
    int t = blockIdx.x * 256 + threadIdx.x;
    if (t >= NE4) return;
    int4 r = ((const int4*)rows)[t];
    int4 c = ((const int4*)cols)[t];
    int p0 = atomicAdd(&g_cnt[r.x], 1);
    int p1 = atomicAdd(&g_cnt[r.y], 1);
    int p2 = atomicAdd(&g_cnt[r.z], 1);
    int p3 = atomicAdd(&g_cnt[r.w], 1);
    if (p0 < SLOT) g_scols[(size_t)r.x * SLOT + p0] = c.x;
    if (p1 < SLOT) g_scols[(size_t)r.y * SLOT + p1] = c.y;
    if (p2 < SLOT) g_scols[(size_t)r.z * SLOT + p2] = c.z;
    if (p3 < SLOT) g_scols[(size_t)r.w * SLOT + p3] = c.w;
}

// ---------------------------------------------------------------------------
// slab3 (all-zeros output plane), on its own stream under the overlap.
// ---------------------------------------------------------------------------
__global__ void __launch_bounds__(256)
zero_slab3_kernel(float* __restrict__ out) {
    size_t idx = (size_t)blockIdx.x * 256 + threadIdx.x;   // N*32 float4
    __stcs(((float4*)out) + 3 * (size_t)N_NODES * 32 + idx,
           make_float4(0.f, 0.f, 0.f, 0.f));
}

// ---------------------------------------------------------------------------
// Fused gather + epilogue: one warp per row; bf16 gather operand (256B/edge).
// Reads cnt from g_cnt, then resets it for the next graph replay.
// ---------------------------------------------------------------------------
__global__ void __launch_bounds__(256)
gather_epilogue_kernel(const float* __restrict__ x, float* __restrict__ out) {
    const int warp = (blockIdx.x * 256 + threadIdx.x) >> 5;
    const int lane = threadIdx.x & 31;
    if (warp >= N_NODES) return;
    const int row = warp;

    int cnt = g_cnt[row];
    if (cnt > SLOT) cnt = SLOT;
    if (lane == 0) g_cnt[row] = 0;     // reset for next launch
    const int base = row * SLOT;

    const uint2* Ib = (const uint2*)g_Ibf;   // 32 uint2 per node row
    float4 a0 = make_float4(0.f, 0.f, 0.f, 0.f);
    float4 a1 = make_float4(0.f, 0.f, 0.f, 0.f);

    int i = 0;
    for (; i + 1 < cnt; i += 2) {
        int c0 = g_scols[base + i];
        int c1 = g_scols[base + i + 1];
        uint2 u0 = Ib[(size_t)c0 * 32 + lane];
        uint2 u1 = Ib[(size_t)c1 * 32 + lane];
        float2 f00 = __bfloat1622float2(*(__nv_bfloat162*)&u0.x);
        float2 f01 = __bfloat1622float2(*(__nv_bfloat162*)&u0.y);
        float2 f10 = __bfloat1622float2(*(__nv_bfloat162*)&u1.x);
        float2 f11 = __bfloat1622float2(*(__nv_bfloat162*)&u1.y);
        a0.x += f00.x; a0.y += f00.y; a0.z += f01.x; a0.w += f01.y;
        a1.x += f10.x; a1.y += f10.y; a1.z += f11.x; a1.w += f11.y;
    }
    if (i < cnt) {
        int c0 = g_scols[base + i];
        uint2 u0 = Ib[(size_t)c0 * 32 + lane];
        float2 f00 = __bfloat1622float2(*(__nv_bfloat162*)&u0.x);
        float2 f01 = __bfloat1622float2(*(__nv_bfloat162*)&u0.y);
        a0.x += f00.x; a0.y += f00.y; a0.z += f01.x; a0.w += f01.y;
    }
    float4 AI;
    AI.x = a0.x + a1.x; AI.y = a0.y + a1.y;
    AI.z = a0.z + a1.z; AI.w = a0.w + a1.w;

    const float beta  = x[((size_t)3 * N_NODES + row) * HID + 0];
    const float gamma = x[((size_t)3 * N_NODES + row) * HID + 1];

    const size_t obase = (size_t)row * 32 + lane;
    const float4* I4 = (const float4*)(g_SI + (size_t)N_NODES * HID);
    float4 S = __ldcs(((const float4*)g_SI) + obase);
    float4 I = __ldcs(I4 + obase);

    float4 dS, dI, dR;
    dS.x = -beta * AI.x * S.x;  dS.y = -beta * AI.y * S.y;
    dS.z = -beta * AI.z * S.z;  dS.w = -beta * AI.w * S.w;
    dI.x = -dS.x - gamma * I.x; dI.y = -dS.y - gamma * I.y;
    dI.z = -dS.z - gamma * I.z; dI.w = -dS.w - gamma * I.w;
    dR.x =  gamma * I.x;        dR.y =  gamma * I.y;
    dR.z =  gamma * I.z;        dR.w =  gamma * I.w;

    float4* o = (float4*)out;
    const size_t slab = (size_t)N_NODES * 32;
    __stcs(o + obase,            dS);
    __stcs(o + slab + obase,     dI);
    __stcs(o + 2 * slab + obase, dR);
}

// ---------------------------------------------------------------------------
// Streams + events, created at load time (outside capture / mem checks).
// ---------------------------------------------------------------------------
namespace {
struct GraphResources {
    cudaStream_t s_sort = nullptr, s_zero = nullptr;
    cudaEvent_t  ev_fork = nullptr, ev_join = nullptr, ev_zero = nullptr;
    GraphResources() {
        int lo = 0, hi = 0;
        cudaDeviceGetStreamPriorityRange(&lo, &hi);   // hi = highest prio
        cudaStreamCreateWithPriority(&s_sort, cudaStreamNonBlocking, hi);
        cudaStreamCreateWithFlags(&s_zero, cudaStreamNonBlocking);
        cudaEventCreateWithFlags(&ev_fork, cudaEventDisableTiming);
        cudaEventCreateWithFlags(&ev_join, cudaEventDisableTiming);
        cudaEventCreateWithFlags(&ev_zero, cudaEventDisableTiming);
    }
};
GraphResources g_res;
}

// ---------------------------------------------------------------------------
extern "C" void kernel_launch(void* const* d_in, const int* in_sizes, int n_in,
                              void* d_out, int out_size) {
    const float* x    = (const float*)d_in[0];
    const float* W    = (const float*)d_in[1];
    const float* b    = (const float*)d_in[2];
    const int*   rows = (const int*)d_in[3];
    const int*   cols = (const int*)d_in[4];
    float*       out  = (float*)d_out;

    const int smem = (3 * 128 * XPAD + 128) * 4;   // 203264 B
    cudaFuncSetAttribute(gemm_tc_kernel,
                         cudaFuncAttributeMaxDynamicSharedMemorySize, smem);

    cudaStream_t s1 = g_res.s_sort;
    cudaStream_t s2 = g_res.s_zero;

    // Fork.
    cudaEventRecord(g_res.ev_fork, 0);
    cudaStreamWaitEvent(s1, g_res.ev_fork, 0);
    cudaStreamWaitEvent(s2, g_res.ev_fork, 0);

    // s2: zero the all-zeros output plane under the overlap window.
    zero_slab3_kernel<<<(N_NODES * 32 + 255) / 256, 256, 0, s2>>>(out);
    cudaEventRecord(g_res.ev_zero, s2);

    // s1: single-pass fixed-slot bucketing (hist+scan+bucket fused).
    const int ebloks = (NE4 + 255) / 256;
    bucket_kernel<<<ebloks, 256, 0, s1>>>(rows, cols);
    cudaEventRecord(g_res.ev_join, s1);

    // Main stream: persistent tf32 tensor-core GEMM (+ bf16 I mirror).
    gemm_tc_kernel<<<GEMM_GRID, 256, smem>>>(x, W, b);

    // Join: gather needs GEMM (stream order) and buckets (event).
    cudaStreamWaitEvent(0, g_res.ev_join, 0);
    gather_epilogue_kernel<<<(N_NODES + 7) / 8, 256>>>(x, out);

    // slab3 completes independently; join it to stream 0 after the gather.
    cudaStreamWaitEvent(0, g_res.ev_zero, 0);
}

// round 17
// speedup vs baseline: 1.7596x; 1.7596x over previous
#include <cuda_runtime.h>
#include <cuda_bf16.h>
#include <cstdint>

#define N_NODES 100000
#define HID     128
#define N_EDGES 1600000
#define SCAN_BLOCKS 98    // 98*1024 = 100352 >= N_NODES
#define NE4 (N_EDGES / 4) // 400000 int4 elements
#define TILES   782       // ceil(100000/128)
#define NJOBS   (2 * TILES)
#define GEMM_GRID 148
#define XPAD 132          // conflict-free tf32 fragment LDS

// Scratch (__device__ globals; zero-initialized at module load; no allocs)
__device__ float          g_SI[2u * N_NODES * HID];     // [0]=S, [1]=I (fp32)
__device__ __nv_bfloat16  g_Ibf[(size_t)N_NODES * HID]; // bf16 mirror of I
__device__ int   g_cnt[N_NODES];               // histogram, then bucket cursor
__device__ int   g_start[N_NODES];             // exclusive prefix (segment start)
__device__ unsigned long long g_tile[SCAN_BLOCKS]; // lookback: (flag<<32)|value
__device__ int   g_scols[N_EDGES];             // cols sorted by destination row

__device__ __forceinline__ unsigned smem_u32(const void* p) {
    unsigned a;
    asm("{ .reg .u64 t; cvta.to.shared.u64 t, %1; cvt.u32.u64 %0, t; }"
        : "=r"(a) : "l"(p));
    return a;
}

__device__ __forceinline__ unsigned to_tf32(float f) {
    unsigned r;
    asm("cvt.rna.tf32.f32 %0, %1;" : "=r"(r) : "f"(f));
    return r;
}

__device__ __forceinline__ void mma_tf32(float* d, const unsigned* a,
                                         const unsigned* b) {
    asm volatile(
        "mma.sync.aligned.m16n8k8.row.col.f32.tf32.tf32.f32 "
        "{%0,%1,%2,%3}, {%4,%5,%6,%7}, {%8,%9}, {%0,%1,%2,%3};\n"
        : "+f"(d[0]), "+f"(d[1]), "+f"(d[2]), "+f"(d[3])
        : "r"(a[0]), "r"(a[1]), "r"(a[2]), "r"(a[3]), "r"(b[0]), "r"(b[1]));
}

// ---------------------------------------------------------------------------
// Persistent tf32 tensor-core GEMM: S/I = sigmoid(x[s] @ W^T + b), s in {0,1}
// s=1 additionally mirrors I to bf16 (gather operand).
// ---------------------------------------------------------------------------
__global__ void __launch_bounds__(256, 1)
gemm_tc_kernel(const float* __restrict__ x,
               const float* __restrict__ W,
               const float* __restrict__ b) {
    extern __shared__ float sm[];
    float* Ws  = sm;                          // 128*XPAD (tf32-rounded bits)
    float* Xs0 = sm + 128 * XPAD;
    float* Xs1 = Xs0 + 128 * XPAD;
    float* Bs  = Xs1 + 128 * XPAD;            // 128

    const int tid  = threadIdx.x;
    const int wid  = tid >> 5;
    const int lane = tid & 31;
    const int qrow = lane >> 2;    // 0..7
    const int qcol = lane & 3;     // 0..3
    const int warpM = wid & 1;     // 2 x 64 rows
    const int warpN = wid >> 1;    // 4 x 32 cols

    for (int idx = tid; idx < 128 * 128; idx += 256) {
        int c = idx >> 7, k = idx & 127;
        Ws[c * XPAD + k] = __uint_as_float(to_tf32(W[idx]));
    }
    if (tid < 128) Bs[tid] = b[tid];

    auto issue_tile = [&](int job, float* dst) {
        const int s    = (job >= TILES) ? 1 : 0;
        const int row0 = (job - s * TILES) * 128;
        const char* src = (const char*)(x + ((size_t)s * N_NODES + row0) * HID);
        unsigned d = smem_u32(dst);
#pragma unroll
        for (int i = 0; i < 16; i++) {
            int c   = tid + i * 256;       // 4096 16B chunks
            int row = c >> 5, col16 = c & 31;
            asm volatile("cp.async.cg.shared.global [%0], [%1], 16;"
                         :: "r"(d + (row * XPAD * 4 + col16 * 16)),
                            "l"(src + (size_t)row * 512 + col16 * 16)
                         : "memory");
        }
        asm volatile("cp.async.commit_group;" ::: "memory");
    };

    int job = blockIdx.x;
    if (job < NJOBS) issue_tile(job, Xs0);
    int buf = 0;

    for (; job < NJOBS; job += GEMM_GRID) {
        const int nxt = job + GEMM_GRID;
        float* Xc = buf ? Xs1 : Xs0;
        if (nxt < NJOBS) {
            issue_tile(nxt, buf ? Xs0 : Xs1);
            asm volatile("cp.async.wait_group 1;" ::: "memory");
        } else {
            asm volatile("cp.async.wait_group 0;" ::: "memory");
        }
        __syncthreads();

        float acc[4][4][4];
#pragma unroll
        for (int i = 0; i < 4; i++)
#pragma unroll
            for (int j = 0; j < 4; j++)
#pragma unroll
                for (int q = 0; q < 4; q++) acc[i][j][q] = 0.f;

#pragma unroll 2
        for (int k0 = 0; k0 < 128; k0 += 8) {
            unsigned af[4][4], bf[4][2];
#pragma unroll
            for (int i = 0; i < 4; i++) {
                const float* base = Xc + (warpM * 64 + i * 16 + qrow) * XPAD + k0 + qcol;
                af[i][0] = to_tf32(base[0]);
                af[i][1] = to_tf32(base[8 * XPAD]);
                af[i][2] = to_tf32(base[4]);
                af[i][3] = to_tf32(base[8 * XPAD + 4]);
            }
#pragma unroll
            for (int j = 0; j < 4; j++) {
                const float* base = Ws + (warpN * 32 + j * 8 + qrow) * XPAD + k0 + qcol;
                bf[j][0] = __float_as_uint(base[0]);
                bf[j][1] = __float_as_uint(base[4]);
            }
#pragma unroll
            for (int i = 0; i < 4; i++)
#pragma unroll
                for (int j = 0; j < 4; j++)
                    mma_tf32(acc[i][j], af[i], bf[j]);
        }

        const int s    = (job >= TILES) ? 1 : 0;
        const int row0 = (job - s * TILES) * 128;
        float* outS = g_SI + ((size_t)s * N_NODES + row0) * HID;
        __nv_bfloat16* outB = g_Ibf + (size_t)row0 * HID;
#pragma unroll
        for (int i = 0; i < 4; i++) {
            const int r0 = warpM * 64 + i * 16 + qrow;
#pragma unroll
            for (int j = 0; j < 4; j++) {
                const int c  = warpN * 32 + j * 8 + 2 * qcol;
                const float b0 = Bs[c], b1 = Bs[c + 1];
                if (row0 + r0 < N_NODES) {
                    float2 v = make_float2(
                        1.f / (1.f + __expf(-(acc[i][j][0] + b0))),
                        1.f / (1.f + __expf(-(acc[i][j][1] + b1))));
                    *(float2*)(outS + (size_t)r0 * HID + c) = v;
                    if (s)
                        *(__nv_bfloat162*)(outB + (size_t)r0 * HID + c) =
                            __float22bfloat162_rn(v);
                }
                if (row0 + r0 + 8 < N_NODES) {
                    float2 v = make_float2(
                        1.f / (1.f + __expf(-(acc[i][j][2] + b0))),
                        1.f / (1.f + __expf(-(acc[i][j][3] + b1))));
                    *(float2*)(outS + (size_t)(r0 + 8) * HID + c) = v;
                    if (s)
                        *(__nv_bfloat162*)(outB + (size_t)(r0 + 8) * HID + c) =
                            __float22bfloat162_rn(v);
                }
            }
        }
        __syncthreads();
        buf ^= 1;
    }
}

// ---------------------------------------------------------------------------
// Counting sort (R12 form): hist -> fused lookback scan -> bucket (dense,
// row-sorted g_scols — this layout is load-bearing for gather locality).
// ---------------------------------------------------------------------------
__global__ void __launch_bounds__(256) hist_kernel(const int* __restrict__ rows) {
    int t = blockIdx.x * 256 + threadIdx.x;
    if (t >= NE4) return;
    int4 r = ((const int4*)rows)[t];
    atomicAdd(&g_cnt[r.x], 1);
    atomicAdd(&g_cnt[r.y], 1);
    atomicAdd(&g_cnt[r.z], 1);
    atomicAdd(&g_cnt[r.w], 1);
}

__global__ void __launch_bounds__(1024) scan_fused_kernel() {
    __shared__ int sh[1024];
    __shared__ int s_prefix;
    const int tid = threadIdx.x;
    const int bid = blockIdx.x;
    const int i   = bid * 1024 + tid;
    const int v   = (i < N_NODES) ? g_cnt[i] : 0;
    sh[tid] = v;
    __syncthreads();
#pragma unroll
    for (int off = 1; off < 1024; off <<= 1) {
        int t = (tid >= off) ? sh[tid - off] : 0;
        __syncthreads();
        sh[tid] += t;
        __syncthreads();
    }
    const int incl     = sh[tid];
    const int blocksum = sh[1023];

    if (tid == 0) {
        if (bid == 0) {
            atomicExch(&g_tile[0], (2ull << 32) | (unsigned)blocksum);
            s_prefix = 0;
        } else {
            atomicExch(&g_tile[bid], (1ull << 32) | (unsigned)blocksum);
            int run = 0;
            int j = bid - 1;
            while (true) {
                unsigned long long t;
                do { t = atomicAdd(&g_tile[j], 0ull); } while ((t >> 32) == 0);
                run += (int)(unsigned)t;
                if ((t >> 32) == 2ull) break;
                j--;
            }
            atomicExch(&g_tile[bid], (2ull << 32) | (unsigned)(run + blocksum));
            s_prefix = run;
        }
    }
    __syncthreads();

    if (i < N_NODES) {
        int excl = incl - v + s_prefix;
        g_start[i] = excl;
        g_cnt[i]   = excl;     // bucket cursor
    }
}

__global__ void __launch_bounds__(256)
bucket_kernel(const int* __restrict__ rows, const int* __restrict__ cols) {
    int t = blockIdx.x * 256 + threadIdx.x;
    if (t >= NE4) return;
    int4 r = ((const int4*)rows)[t];
    int4 c = ((const int4*)cols)[t];
    int p0 = atomicAdd(&g_cnt[r.x], 1);
    int p1 = atomicAdd(&g_cnt[r.y], 1);
    int p2 = atomicAdd(&g_cnt[r.z], 1);
    int p3 = atomicAdd(&g_cnt[r.w], 1);
    g_scols[p0] = c.x;
    g_scols[p1] = c.y;
    g_scols[p2] = c.z;
    g_scols[p3] = c.w;
}

// ---------------------------------------------------------------------------
// slab3 (all-zeros output plane), on its own stream under the overlap.
// ---------------------------------------------------------------------------
__global__ void __launch_bounds__(256)
zero_slab3_kernel(float* __restrict__ out) {
    size_t idx = (size_t)blockIdx.x * 256 + threadIdx.x;   // N*32 float4
    __stcs(((float4*)out) + 3 * (size_t)N_NODES * 32 + idx,
           make_float4(0.f, 0.f, 0.f, 0.f));
}

// ---------------------------------------------------------------------------
// Fused gather + epilogue: one warp per row; bf16 gather operand.
// MLP-4: four index loads issued as a batch ahead of four value loads
// (no shfl). Resets g_cnt / g_tile for the next graph replay.
// ---------------------------------------------------------------------------
__global__ void __launch_bounds__(256)
gather_epilogue_kernel(const float* __restrict__ x, float* __restrict__ out) {
    if (blockIdx.x == 0 && threadIdx.x < SCAN_BLOCKS)
        g_tile[threadIdx.x] = 0ull;

    const int warp = (blockIdx.x * 256 + threadIdx.x) >> 5;
    const int lane = threadIdx.x & 31;
    if (warp >= N_NODES) return;
    const int row = warp;

    const int s0 = g_start[row];
    const int s1 = (row + 1 < N_NODES) ? g_start[row + 1] : N_EDGES;
    if (lane == 0) g_cnt[row] = 0;     // reset histogram for next launch

    const uint2* Ib = (const uint2*)g_Ibf;   // 32 uint2 per node row
    float4 a0 = make_float4(0.f, 0.f, 0.f, 0.f);
    float4 a1 = make_float4(0.f, 0.f, 0.f, 0.f);

    int i = s0;
    for (; i + 3 < s1; i += 4) {
        int c0 = g_scols[i];
        int c1 = g_scols[i + 1];
        int c2 = g_scols[i + 2];
        int c3 = g_scols[i + 3];
        uint2 u0 = Ib[(size_t)c0 * 32 + lane];
        uint2 u1 = Ib[(size_t)c1 * 32 + lane];
        uint2 u2 = Ib[(size_t)c2 * 32 + lane];
        uint2 u3 = Ib[(size_t)c3 * 32 + lane];
        float2 f00 = __bfloat1622float2(*(__nv_bfloat162*)&u0.x);
        float2 f01 = __bfloat1622float2(*(__nv_bfloat162*)&u0.y);
        float2 f10 = __bfloat1622float2(*(__nv_bfloat162*)&u1.x);
        float2 f11 = __bfloat1622float2(*(__nv_bfloat162*)&u1.y);
        float2 f20 = __bfloat1622float2(*(__nv_bfloat162*)&u2.x);
        float2 f21 = __bfloat1622float2(*(__nv_bfloat162*)&u2.y);
        float2 f30 = __bfloat1622float2(*(__nv_bfloat162*)&u3.x);
        float2 f31 = __bfloat1622float2(*(__nv_bfloat162*)&u3.y);
        a0.x += f00.x; a0.y += f00.y; a0.z += f01.x; a0.w += f01.y;
        a1.x += f10.x; a1.y += f10.y; a1.z += f11.x; a1.w += f11.y;
        a0.x += f20.x; a0.y += f20.y; a0.z += f21.x; a0.w += f21.y;
        a1.x += f30.x; a1.y += f30.y; a1.z += f31.x; a1.w += f31.y;
    }
    for (; i < s1; i++) {
        int c0 = g_scols[i];
        uint2 u0 = Ib[(size_t)c0 * 32 + lane];
        float2 f00 = __bfloat1622float2(*(__nv_bfloat162*)&u0.x);
        float2 f01 = __bfloat1622float2(*(__nv_bfloat162*)&u0.y);
        a0.x += f00.x; a0.y += f00.y; a0.z += f01.x; a0.w += f01.y;
    }
    float4 AI;
    AI.x = a0.x + a1.x; AI.y = a0.y + a1.y;
    AI.z = a0.z + a1.z; AI.w = a0.w + a1.w;

    const float beta  = x[((size_t)3 * N_NODES + row) * HID + 0];
    const float gamma = x[((size_t)3 * N_NODES + row) * HID + 1];

    const size_t base = (size_t)row * 32 + lane;
    const float4* I4 = (const float4*)(g_SI + (size_t)N_NODES * HID);
    float4 S = __ldcs(((const float4*)g_SI) + base);
    float4 I = __ldcs(I4 + base);

    float4 dS, dI, dR;
    dS.x = -beta * AI.x * S.x;  dS.y = -beta * AI.y * S.y;
    dS.z = -beta * AI.z * S.z;  dS.w = -beta * AI.w * S.w;
    dI.x = -dS.x - gamma * I.x; dI.y = -dS.y - gamma * I.y;
    dI.z = -dS.z - gamma * I.z; dI.w = -dS.w - gamma * I.w;
    dR.x =  gamma * I.x;        dR.y =  gamma * I.y;
    dR.z =  gamma * I.z;        dR.w =  gamma * I.w;

    float4* o = (float4*)out;
    const size_t slab = (size_t)N_NODES * 32;
    __stcs(o + base,            dS);
    __stcs(o + slab + base,     dI);
    __stcs(o + 2 * slab + base, dR);
}

// ---------------------------------------------------------------------------
// Streams + events, created at load time (outside capture / mem checks).
// ---------------------------------------------------------------------------
namespace {
struct GraphResources {
    cudaStream_t s_sort = nullptr, s_zero = nullptr;
    cudaEvent_t  ev_fork = nullptr, ev_join = nullptr, ev_zero = nullptr;
    GraphResources() {
        int lo = 0, hi = 0;
        cudaDeviceGetStreamPriorityRange(&lo, &hi);   // hi = highest prio
        cudaStreamCreateWithPriority(&s_sort, cudaStreamNonBlocking, hi);
        cudaStreamCreateWithFlags(&s_zero, cudaStreamNonBlocking);
        cudaEventCreateWithFlags(&ev_fork, cudaEventDisableTiming);
        cudaEventCreateWithFlags(&ev_join, cudaEventDisableTiming);
        cudaEventCreateWithFlags(&ev_zero, cudaEventDisableTiming);
    }
};
GraphResources g_res;
}

// ---------------------------------------------------------------------------
extern "C" void kernel_launch(void* const* d_in, const int* in_sizes, int n_in,
                              void* d_out, int out_size) {
    const float* x    = (const float*)d_in[0];
    const float* W    = (const float*)d_in[1];
    const float* b    = (const float*)d_in[2];
    const int*   rows = (const int*)d_in[3];
    const int*   cols = (const int*)d_in[4];
    float*       out  = (float*)d_out;

    const int smem = (3 * 128 * XPAD + 128) * 4;   // 203264 B
    cudaFuncSetAttribute(gemm_tc_kernel,
                         cudaFuncAttributeMaxDynamicSharedMemorySize, smem);

    cudaStream_t s1 = g_res.s_sort;
    cudaStream_t s2 = g_res.s_zero;

    // Fork.
    cudaEventRecord(g_res.ev_fork, 0);
    cudaStreamWaitEvent(s1, g_res.ev_fork, 0);
    cudaStreamWaitEvent(s2, g_res.ev_fork, 0);

    // s2: zero the all-zeros output plane under the overlap window.
    zero_slab3_kernel<<<(N_NODES * 32 + 255) / 256, 256, 0, s2>>>(out);
    cudaEventRecord(g_res.ev_zero, s2);

    // s1: counting sort (hist -> fused scan -> bucket), dense sorted layout.
    const int ebloks = (NE4 + 255) / 256;
    hist_kernel<<<ebloks, 256, 0, s1>>>(rows);
    scan_fused_kernel<<<SCAN_BLOCKS, 1024, 0, s1>>>();
    bucket_kernel<<<ebloks, 256, 0, s1>>>(rows, cols);
    cudaEventRecord(g_res.ev_join, s1);

    // Main stream: persistent tf32 tensor-core GEMM (+ bf16 I mirror).
    gemm_tc_kernel<<<GEMM_GRID, 256, smem>>>(x, W, b);

    // Join: gather needs GEMM (stream order), sort and slab3 (events).
    cudaStreamWaitEvent(0, g_res.ev_join, 0);
    cudaStreamWaitEvent(0, g_res.ev_zero, 0);
    gather_epilogue_kernel<<<(N_NODES + 7) / 8, 256>>>(x, out);
}